// round 6
// baseline (speedup 1.0000x reference)
#include <cuda_runtime.h>

#define TPB 256
#define MAX_BLOCKS 8192

__device__ float g_partials[MAX_BLOCKS];
__device__ unsigned int g_count = 0;

__device__ __forceinline__ float compute_iou(float bx, float by, float bw, float bh,
                                             float lx, float ly, float lw, float lh) {
    const float invS = 1.0f / 7.0f;
    float x1 = bx * invS - bw * 0.5f;
    float y1 = by * invS - bh * 0.5f;
    float x2 = bx * invS + bw * 0.5f;
    float y2 = by * invS + bh * 0.5f;
    float u1 = lx * invS - lw * 0.5f;
    float v1 = ly * invS - lh * 0.5f;
    float u2 = lx * invS + lw * 0.5f;
    float v2 = ly * invS + lh * 0.5f;
    float a1 = (x2 - x1) * (y2 - y1);
    float a2 = (u2 - u1) * (v2 - v1);
    float left   = fmaxf(x1, u1);
    float right  = fminf(x2, u2);
    float top    = fmaxf(y1, v1);
    float bottom = fminf(y2, v2);
    bool valid = (left < right) && (top < bottom);
    float inter = valid ? (right - left) * (bottom - top) : 0.0f;
    float uni = a1 + a2 - inter;
    return valid ? (inter / uni) : 0.0f;
}

__device__ __forceinline__ float cell_loss(const float* __restrict__ predict,
                                           const float* __restrict__ label,
                                           int cell) {
    const float* pbase = predict + (size_t)cell * 26;
    const float* lbase = label   + (size_t)cell * 26;

    float l4 = __ldg(lbase + 4);
    float p4 = __ldg(pbase + 4);
    float p9 = __ldg(pbase + 9);

    if (l4 == 0.0f) {
        // noobj cell (~96%)
        return 0.5f * (p4 * p4 + p9 * p9);
    }

    // coord cell (~4%) — float2 streaming, no local arrays
    const float2* pp = reinterpret_cast<const float2*>(pbase);
    const float2* lp = reinterpret_cast<const float2*>(lbase);

    float2 p01 = __ldg(pp + 0);
    float2 p23 = __ldg(pp + 1);
    float2 p45 = __ldg(pp + 2);
    float2 p67 = __ldg(pp + 3);
    float2 p89 = __ldg(pp + 4);
    float2 l01 = __ldg(lp + 0);
    float2 l23 = __ldg(lp + 1);

    float cls = 0.0f;
#pragma unroll
    for (int j = 5; j < 13; j++) {
        float2 pv = __ldg(pp + j);
        float2 lv = __ldg(lp + j);
        float dx = pv.x - lv.x;
        float dy = pv.y - lv.y;
        cls += dx * dx + dy * dy;
    }

    float iou1 = compute_iou(p01.x, p01.y, p23.x, p23.y,
                             l01.x, l01.y, l23.x, l23.y);
    float iou2 = compute_iou(p45.y, p67.x, p67.y, p89.x,
                             l01.x, l01.y, l23.x, l23.y);
    bool pick1 = iou1 > iou2;

    float s0 = pick1 ? p01.x : p45.y;
    float s1 = pick1 ? p01.y : p67.x;
    float s2 = pick1 ? p23.x : p67.y;
    float s3 = pick1 ? p23.y : p89.x;

    float d0 = s0 - l01.x;
    float d1 = s1 - l01.y;
    float d2 = sqrtf(s2) - sqrtf(l23.x);
    float d3 = sqrtf(s3) - sqrtf(l23.y);
    float coord_cell = d0 * d0 + d1 * d1 + d2 * d2 + d3 * d3;

    float c  = pick1 ? p45.x : p89.y;
    float io = pick1 ? iou1  : iou2;
    float dc = c - io;
    float obj_c_cell = dc * dc;

    float other = pick1 ? p89.y : p45.x;
    float noobj_extra = other * other;

    return 5.0f * coord_cell + obj_c_cell + 0.5f * noobj_extra + cls;
}

__global__ void __launch_bounds__(TPB)
yolo_fused_kernel(const float* __restrict__ predict,
                  const float* __restrict__ label,
                  int ncells, float invN,
                  float* __restrict__ out) {
    const int tid = threadIdx.x;
    const int gtid = blockIdx.x * TPB + tid;
    const int stride = gridDim.x * TPB;

    float loss = 0.0f;
    // 2 cells per thread (grid sized so stride*2 >= ncells)
    if (gtid < ncells)          loss  = cell_loss(predict, label, gtid);
    if (gtid + stride < ncells) loss += cell_loss(predict, label, gtid + stride);

    // ---- block reduction ----
    __shared__ float sm[TPB / 32];
    __shared__ bool s_last;
    float s = loss;
#pragma unroll
    for (int o = 16; o > 0; o >>= 1)
        s += __shfl_down_sync(0xFFFFFFFFu, s, o);
    if ((tid & 31) == 0)
        sm[tid >> 5] = s;
    __syncthreads();
    if (tid < 32) {
        s = (tid < (TPB / 32)) ? sm[tid] : 0.0f;
#pragma unroll
        for (int o = 16; o > 0; o >>= 1)
            s += __shfl_down_sync(0xFFFFFFFFu, s, o);
        if (tid == 0) {
            g_partials[blockIdx.x] = s;
            // acq_rel atomic: release orders the partial store above,
            // acquire (for the last arriver) makes all partials visible.
            // No __threadfence, no L1 invalidate. Wraps to 0 -> graph-replay safe.
            unsigned int old;
            asm volatile("atom.acq_rel.gpu.global.inc.u32 %0, [%1], %2;"
                         : "=r"(old)
                         : "l"(&g_count), "r"(gridDim.x - 1)
                         : "memory");
            s_last = (old == gridDim.x - 1);
        }
    }
    __syncthreads();

    // ---- last-arriving block: deterministic final reduction ----
    if (s_last) {
        float t = 0.0f;
        for (int i = tid; i < (int)gridDim.x; i += TPB)
            t += __ldcg(&g_partials[i]);   // L2-direct read of partials
#pragma unroll
        for (int o = 16; o > 0; o >>= 1)
            t += __shfl_down_sync(0xFFFFFFFFu, t, o);
        if ((tid & 31) == 0)
            sm[tid >> 5] = t;
        __syncthreads();
        if (tid < 32) {
            t = (tid < (TPB / 32)) ? sm[tid] : 0.0f;
#pragma unroll
            for (int o = 16; o > 0; o >>= 1)
                t += __shfl_down_sync(0xFFFFFFFFu, t, o);
            if (tid == 0)
                out[0] = t * invN;
        }
    }
}

extern "C" void kernel_launch(void* const* d_in, const int* in_sizes, int n_in,
                              void* d_out, int out_size) {
    const float* predict = (const float*)d_in[0];
    const float* label   = (const float*)d_in[1];
    float* out = (float*)d_out;

    int total  = in_sizes[0];          // B*7*7*26
    int ncells = total / 26;           // B*49
    // 2 cells per thread
    int nblocks = (ncells + 2 * TPB - 1) / (2 * TPB);
    if (nblocks > MAX_BLOCKS) nblocks = MAX_BLOCKS;  // never hit for this shape

    float invN = 49.0f / (float)ncells;  // 1 / batch

    yolo_fused_kernel<<<nblocks, TPB>>>(predict, label, ncells, invN, out);
}